// round 8
// baseline (speedup 1.0000x reference)
#include <cuda_runtime.h>
#include <cuda_pipeline_primitives.h>

// CGMMTransition: N=10000, L=5, A=6, C=20, C2=20
// Persistent (static-stride) kernel, 8 CTAs/SM, cp.async double-buffered stats.
// Outputs (concatenated in d_out, fp32):
//   p_Q_given_obs        [N, C]           at offset 0
//   transition_posterior [N, L, A, C, C2] at offset N*C
//   rightmost_term       [N, L, A, C, C2] at offset N*C + N*L*A*C*C2

#define LVAL   5
#define AVAL   6
#define CVAL   20
#define C2VAL  20
#define LA     30      // L*A
#define KDIM   600     // LA*C2
#define PER_N  12000   // LA*C*C2
#define PER_N4 3000    // PER_N/4
#define NTHREADS 256
#define NWARPS 8
#define NITER  12      // ceil(3000/256); iter 11 partial (tid < 184)
#define TAIL   (PER_N4 - 11 * NTHREADS)   // 184
#define GRID   1216    // 152 SMs x 8 CTAs

__global__ void __launch_bounds__(NTHREADS, 8)
cgmm_kernel(const float* __restrict__ stats,
            const float* __restrict__ layerS,
            const float* __restrict__ arcS,
            const float* __restrict__ T,
            float* __restrict__ out_pq,
            float* __restrict__ out_tp,
            float* __restrict__ out_rt,
            int N)
{
    __shared__ float s_stats[2][KDIM];
    __shared__ float s_inv[2][LA];
    __shared__ float s_w[LA];
    __shared__ float s_pqw[NWARPS][CVAL];   // per-warp c-bins (non-atomic)

    const int tid  = threadIdx.x;
    const int warp = tid >> 5;
    const int lane = tid & 31;

    // ---- prologue: fetch stats(bid) into bank 0; one-time setup ----
    if (tid < KDIM / 4)
        __pipeline_memcpy_async(&s_stats[0][tid * 4],
                                stats + (size_t)blockIdx.x * KDIM + tid * 4, 16);
    __pipeline_commit();

    if (tid < LA) s_w[tid] = layerS[tid / AVAL] * arcS[tid];
    if (tid < NWARPS * CVAL) reinterpret_cast<float*>(s_pqw)[tid] = 0.0f;

    __pipeline_wait_prior(0);
    __syncthreads();
    if (tid < LA) {
        float s = 0.0f;
        #pragma unroll
        for (int j = 0; j < C2VAL; ++j) s += s_stats[0][tid * C2VAL + j];
        s_inv[0][tid] = (s == 0.0f) ? 1.0f : 1.0f / s;
    }
    __syncthreads();

    int b = 0;
    for (int n = blockIdx.x; n < N; n += GRID) {
        const int n_next = n + GRID;
        // prefetch next n's stats into the other bank (latency hides under stream)
        if (n_next < N && tid < KDIM / 4)
            __pipeline_memcpy_async(&s_stats[b ^ 1][tid * 4],
                                    stats + (size_t)n_next * KDIM + tid * 4, 16);
        __pipeline_commit();

        // ---- main elementwise stream for n (identical to R6 body) ----
        const size_t base = (size_t)n * PER_N;   // 48000 B -> 16B aligned
        const float4* T4  = reinterpret_cast<const float4*>(T);
        float4* rt4 = reinterpret_cast<float4*>(out_rt + base);
        float4* tp4 = reinterpret_cast<float4*>(out_tp + base);

        // division-free index state for i = tid + 256*k (element e = 4*i)
        int m    = tid % 5;                 // c2 block = 4*m
        int c    = (tid / 5) % CVAL;
        int la   = tid / 100;
        int r100 = tid % 100;

        #pragma unroll
        for (int k = 0; k < NITER; ++k) {
            const int  i   = tid + k * NTHREADS;
            const bool act = (k < NITER - 1) || (tid < TAIL);

            float v = 0.0f;
            if (act) {
                const float4 t  = __ldg(&T4[i]);   // L1-resident, coalesced
                const float4 sv = *reinterpret_cast<const float4*>(
                                      s_stats[b] + la * C2VAL + 4 * m);
                const float inv = s_inv[b][la];
                const float w   = s_w[la];
                float4 r, p;
                r.x = t.x * sv.x * inv;  r.y = t.y * sv.y * inv;
                r.z = t.z * sv.z * inv;  r.w = t.w * sv.w * inv;
                p.x = r.x * w;  p.y = r.y * w;  p.z = r.z * w;  p.w = r.w * w;
                __stcs(&rt4[i], r);   // streaming stores
                __stcs(&tp4[i], p);
                v = (p.x + p.y) + (p.z + p.w);
            }

            // segmented reduction over runs of 5 equal-c lanes (d = 1,2,4)
            float o;
            o = __shfl_down_sync(0xFFFFFFFFu, v, 1);
            if (m <= 3 && lane < 31) v += o;
            o = __shfl_down_sync(0xFFFFFFFFu, v, 2);
            if (m <= 2 && lane < 30) v += o;
            o = __shfl_down_sync(0xFFFFFFFFu, v, 4);
            if (m == 0 && lane < 28) v += o;

            // head lanes have distinct c within a warp-iter -> plain RMW safe
            if (m == 0 || lane == 0) s_pqw[warp][c] += v;

            const bool wrap = (m == 4);
            m = wrap ? 0 : m + 1;
            c += wrap ? 12 : 11;
            if (c >= CVAL) c -= CVAL;
            la += 2; r100 += 56;
            if (r100 >= 100) { la += 1; r100 -= 100; }
        }

        __pipeline_wait_prior(0);   // prefetched bank staged (per-thread)
        __syncthreads();            // A: stream + pqw bins + staging complete

        // p_Q readout for n; zero bins for next n
        if (tid < CVAL) {
            float s = 0.0f;
            #pragma unroll
            for (int w8 = 0; w8 < NWARPS; ++w8) {
                s += s_pqw[w8][tid];
                s_pqw[w8][tid] = 0.0f;
            }
            out_pq[(size_t)n * CVAL + tid] = s;
        }
        // inv for the next n from the freshly staged bank
        if (n_next < N && tid < LA) {
            float s = 0.0f;
            #pragma unroll
            for (int j = 0; j < C2VAL; ++j) s += s_stats[b ^ 1][tid * C2VAL + j];
            s_inv[b ^ 1][tid] = (s == 0.0f) ? 1.0f : 1.0f / s;
        }
        b ^= 1;
        __syncthreads();            // B: bins zeroed + inv visible
    }
}

extern "C" void kernel_launch(void* const* d_in, const int* in_sizes, int n_in,
                              void* d_out, int out_size)
{
    const float* stats  = (const float*)d_in[0];  // [N, L, A, C2]
    const float* layerS = (const float*)d_in[1];  // [L]
    const float* arcS   = (const float*)d_in[2];  // [L, A]
    const float* T      = (const float*)d_in[3];  // [L, A, C, C2]

    const int N = in_sizes[0] / KDIM;

    float* out    = (float*)d_out;
    float* out_pq = out;
    float* out_tp = out_pq + (size_t)N * CVAL;
    float* out_rt = out_tp + (size_t)N * PER_N;

    cgmm_kernel<<<GRID, NTHREADS>>>(stats, layerS, arcS, T,
                                    out_pq, out_tp, out_rt, N);
}